// round 7
// baseline (speedup 1.0000x reference)
#include <cuda_runtime.h>
#include <cstddef>
#include <cstdint>

#define HH 320
#define WW 320
#define CC 64
#define BB 2
#define HW (HH*WW)              // 102400
#define CHW ((size_t)CC*HW)     // 6553600
#define TENSOR_ELEMS (BB*CHW)   // 13107200

// Scratch (static device arrays; no allocation allowed)
__device__ uint32_t g_Mt[2*CC*CC];           // tf32(M^T) per dir
__device__ uint32_t g_buf[2][TENSOR_ELEMS];  // buffer_d, buffer_u (tf32 bits)
__device__ uint32_t g_t[2][TENSOR_ELEMS];    // relu(conv1) intermediates (tf32 bits)
__device__ uint32_t g_utf[TENSOR_ELEMS];     // tf32(u)
__device__ uint32_t g_dtf[TENSOR_ELEMS];     // tf32(d)
// pre-permuted tf32 weights: [chunk][tap][o][18]
__device__ uint32_t g_wp1a[8*9*64*18];
__device__ uint32_t g_wp2a[8*9*64*18];
__device__ uint32_t g_wp1b[4*9*64*18];
__device__ uint32_t g_wp2b[4*9*64*18];

__device__ __forceinline__ uint32_t f2tf32(float f) {
    uint32_t r; asm("cvt.rna.tf32.f32 %0, %1;" : "=r"(r) : "f"(f)); return r;
}
__device__ __forceinline__ void mma_tf32(float4& d,
        uint32_t a0, uint32_t a1, uint32_t a2, uint32_t a3,
        uint32_t b0, uint32_t b1) {
    asm("mma.sync.aligned.m16n8k8.row.col.f32.tf32.tf32.f32 "
        "{%0,%1,%2,%3}, {%4,%5,%6,%7}, {%8,%9}, {%0,%1,%2,%3};"
        : "+f"(d.x), "+f"(d.y), "+f"(d.z), "+f"(d.w)
        : "r"(a0), "r"(a1), "r"(a2), "r"(a3), "r"(b0), "r"(b1));
}
__device__ __forceinline__ void cp16(uint32_t saddr, const void* gaddr, uint32_t sz) {
    asm volatile("cp.async.cg.shared.global [%0], [%1], 16, %2;"
                 :: "r"(saddr), "l"(gaddr), "r"(sz));
}
__device__ __forceinline__ uint32_t fu(float f) { return __float_as_uint(f); }

// ---------------------------------------------------------------------------
// prep kernels
// ---------------------------------------------------------------------------
__global__ void kprepin(const float* __restrict__ u, const float* __restrict__ d) {
    for (size_t i = (size_t)blockIdx.x*256 + threadIdx.x; i < TENSOR_ELEMS;
         i += (size_t)gridDim.x*256) {
        g_utf[i] = f2tf32(u[i]);
        g_dtf[i] = f2tf32(d[i]);
    }
}

__global__ void kprepw(const float* __restrict__ W, uint32_t* __restrict__ dst, int cin) {
    int total = (cin/16)*9*64*18;
    for (int i = blockIdx.x*256 + threadIdx.x; i < total; i += gridDim.x*256) {
        int w    = i % 18;
        int rest = i / 18;
        int o    = rest % 64;
        int rest2= rest / 64;
        int t    = rest2 % 9;
        int chunk= rest2 / 9;
        uint32_t v = 0;
        if (w < 16) {
            int s = w >> 3, p = w & 7;
            int c = (p >> 1) + ((p & 1) << 2);
            int cinidx = chunk*16 + s*8 + c;
            v = f2tf32(W[(size_t)o*(cin*9) + (size_t)cinidx*9 + t]);
        }
        dst[i] = v;
    }
}

__global__ void kcomputeM(const float* __restrict__ Wq,
                          const float* __restrict__ Wk, int dir) {
    __shared__ float sq[64*64];
    __shared__ float sk[64*64];
    int t = threadIdx.x;
    for (int i = t; i < 4096; i += 256) { sq[i] = Wq[i]; sk[i] = Wk[i]; }
    __syncthreads();
    for (int i = t; i < 4096; i += 256) {
        int a = i >> 6, b = i & 63;
        float s = 0.f;
        #pragma unroll 16
        for (int c = 0; c < 64; c++) s += sq[c*64 + a] * sk[c*64 + b];
        g_Mt[dir*4096 + b*64 + a] = f2tf32(s);
    }
}

// ---------------------------------------------------------------------------
// Kernel 2: tensor-core axial attention (unchanged from R5)
// ---------------------------------------------------------------------------
#define ATTN_SMEM ((64*328*2 + 32*328 + 64*36)*4)   // 219136 B

__global__ __launch_bounds__(256)
void kattn(int dummy) {
    extern __shared__ float smem[];
    float* su = smem;                 // 64*328
    float* sd = su + 64*328;
    float* sP = sd + 64*328;          // 32*328
    float* sR = sP + 32*328;          // 64*36

    int tid  = threadIdx.x;
    int lane = tid & 31, warp = tid >> 5;
    int gid  = lane >> 2, tid4 = lane & 3;
    int b = blockIdx.x / HH, h = blockIdx.x % HH;
    const uint32_t* ub = g_utf + (size_t)b*CHW + (size_t)h*WW;
    const uint32_t* db = g_dtf + (size_t)b*CHW + (size_t)h*WW;

    for (int i = tid; i < 64*80; i += 256) {
        int c = i / 80, q4 = (i % 80) * 4;
        uint4 vu = *(const uint4*)(ub + (size_t)c*HW + q4);
        uint4 vd = *(const uint4*)(db + (size_t)c*HW + q4);
        *(uint4*)&su[c*328 + q4] = vu;
        *(uint4*)&sd[c*328 + q4] = vd;
    }

    for (int dir = 0; dir < 2; dir++) {
        const float* sQ = dir ? sd : su;
        const float* sV = dir ? su : sd;
        uint32_t* outg = g_buf[dir] + (size_t)b*CHW + (size_t)h*WW;

        const uint32_t* Mt = g_Mt + dir*4096;
        int bg = warp & 3, qh = warp >> 2;
        uint32_t am[8][4];
        {
            int r = bg*16 + gid;
            #pragma unroll
            for (int k = 0; k < 8; k++) {
                int c0 = k*8 + tid4;
                am[k][0] = Mt[r*64 + c0];
                am[k][1] = Mt[(r+8)*64 + c0];
                am[k][2] = Mt[r*64 + c0 + 4];
                am[k][3] = Mt[(r+8)*64 + c0 + 4];
            }
        }

        for (int q0 = 0; q0 < WW; q0 += 32) {
            __syncthreads();

            float4 rc[2];
            rc[0] = make_float4(0.f,0.f,0.f,0.f);
            rc[1] = make_float4(0.f,0.f,0.f,0.f);
            #pragma unroll
            for (int k = 0; k < 8; k++) {
                #pragma unroll
                for (int nt = 0; nt < 2; nt++) {
                    int qq = q0 + qh*16 + nt*8 + gid;
                    uint32_t b0 = fu(sQ[(k*8 + tid4)*328 + qq]);
                    uint32_t b1 = fu(sQ[(k*8 + tid4 + 4)*328 + qq]);
                    mma_tf32(rc[nt], am[k][0], am[k][1], am[k][2], am[k][3], b0, b1);
                }
            }
            #pragma unroll
            for (int nt = 0; nt < 2; nt++) {
                int q = qh*16 + nt*8 + 2*tid4;
                int bb = bg*16 + gid;
                *(uint2*)&sR[bb*36 + q]     = make_uint2(f2tf32(rc[nt].x), f2tf32(rc[nt].y));
                *(uint2*)&sR[(bb+8)*36 + q] = make_uint2(f2tf32(rc[nt].z), f2tf32(rc[nt].w));
            }
            __syncthreads();

            {
                int qg = warp >> 2, vg = warp & 3;
                float4 sc[10];
                #pragma unroll
                for (int nt = 0; nt < 10; nt++) sc[nt] = make_float4(0.f,0.f,0.f,0.f);
                #pragma unroll
                for (int k = 0; k < 8; k++) {
                    uint32_t a0 = fu(sR[(k*8 + tid4)*36 + qg*16 + gid]);
                    uint32_t a1 = fu(sR[(k*8 + tid4)*36 + qg*16 + gid + 8]);
                    uint32_t a2 = fu(sR[(k*8 + tid4 + 4)*36 + qg*16 + gid]);
                    uint32_t a3 = fu(sR[(k*8 + tid4 + 4)*36 + qg*16 + gid + 8]);
                    #pragma unroll
                    for (int nt = 0; nt < 10; nt++) {
                        int vv = vg*80 + nt*8 + gid;
                        uint32_t b0 = fu(sV[(k*8 + tid4)*328 + vv]);
                        uint32_t b1 = fu(sV[(k*8 + tid4 + 4)*328 + vv]);
                        mma_tf32(sc[nt], a0, a1, a2, a3, b0, b1);
                    }
                }
                #pragma unroll
                for (int nt = 0; nt < 10; nt++) {
                    int q = qg*16 + gid, v = vg*80 + nt*8 + 2*tid4;
                    *(float2*)&sP[q*328 + v]     = make_float2(sc[nt].x, sc[nt].y);
                    *(float2*)&sP[(q+8)*328 + v] = make_float2(sc[nt].z, sc[nt].w);
                }
            }
            __syncthreads();

            #pragma unroll
            for (int i = 0; i < 4; i++) {
                int row = warp*4 + i;
                float a[10];
                #pragma unroll
                for (int j = 0; j < 10; j++) a[j] = sP[row*328 + lane + 32*j];
                float m = a[0];
                #pragma unroll
                for (int j = 1; j < 10; j++) m = fmaxf(m, a[j]);
                #pragma unroll
                for (int o = 16; o > 0; o >>= 1) m = fmaxf(m, __shfl_xor_sync(~0u, m, o));
                float s = 0.f;
                #pragma unroll
                for (int j = 0; j < 10; j++) { a[j] = __expf(a[j] - m); s += a[j]; }
                #pragma unroll
                for (int o = 16; o > 0; o >>= 1) s += __shfl_xor_sync(~0u, s, o);
                float inv = 1.f / s;
                #pragma unroll
                for (int j = 0; j < 10; j++)
                    sP[row*328 + lane + 32*j] = __uint_as_float(f2tf32(a[j]*inv));
            }
            __syncthreads();

            {
                int cg = warp & 3, kh = warp >> 2;
                float4 oc[4];
                #pragma unroll
                for (int nt = 0; nt < 4; nt++) oc[nt] = make_float4(0.f,0.f,0.f,0.f);
                #pragma unroll
                for (int k = 0; k < 20; k++) {
                    int kb = kh*160 + k*8;
                    uint32_t a0 = fu(sV[(cg*16 + gid)*328 + kb + tid4]);
                    uint32_t a1 = fu(sV[(cg*16 + gid + 8)*328 + kb + tid4]);
                    uint32_t a2 = fu(sV[(cg*16 + gid)*328 + kb + tid4 + 4]);
                    uint32_t a3 = fu(sV[(cg*16 + gid + 8)*328 + kb + tid4 + 4]);
                    #pragma unroll
                    for (int nt = 0; nt < 4; nt++) {
                        uint32_t b0 = fu(sP[(nt*8 + gid)*328 + kb + tid4]);
                        uint32_t b1 = fu(sP[(nt*8 + gid)*328 + kb + tid4 + 4]);
                        mma_tf32(oc[nt], a0, a1, a2, a3, b0, b1);
                    }
                }
                if (kh == 0) {
                    #pragma unroll
                    for (int nt = 0; nt < 4; nt++) {
                        int c = cg*16 + gid, q = nt*8 + 2*tid4;
                        *(float2*)&sR[c*36 + q]     = make_float2(oc[nt].x, oc[nt].y);
                        *(float2*)&sR[(c+8)*36 + q] = make_float2(oc[nt].z, oc[nt].w);
                    }
                }
                __syncthreads();
                if (kh == 1) {
                    #pragma unroll
                    for (int nt = 0; nt < 4; nt++) {
                        int c = cg*16 + gid, q = nt*8 + 2*tid4;
                        float2 r0 = *(const float2*)&sR[c*36 + q];
                        float2 r1 = *(const float2*)&sR[(c+8)*36 + q];
                        uint2 w0 = make_uint2(f2tf32(oc[nt].x + r0.x), f2tf32(oc[nt].y + r0.y));
                        uint2 w1 = make_uint2(f2tf32(oc[nt].z + r1.x), f2tf32(oc[nt].w + r1.y));
                        *(uint2*)(outg + (size_t)c*HW + q0 + q)     = w0;
                        *(uint2*)(outg + (size_t)(c+8)*HW + q0 + q) = w1;
                    }
                }
            }
        }
        __syncthreads();
    }
}

// ---------------------------------------------------------------------------
// Kernel 3: tf32 implicit-GEMM 3x3 conv, double-buffered cp.async pipeline.
// Block = 512 thr, tile 64x x 8y, both streams via blockIdx.z = (s<<1)|b.
// Input smem plane stride 728 (=24 mod 32 -> conflict-free B LDS.32).
// ---------------------------------------------------------------------------
#define PLANE 728
#define SIN_U32 (16*PLANE)              // 11648
#define SW_U32  (9*64*18)               // 10368
#define STAGE_U32 (SIN_U32 + SW_U32)    // 22016
#define CONV_SMEM (STAGE_U32*2*4)       // 176128 bytes

template<int CIN, bool FUSE>
__global__ __launch_bounds__(512, 1)
void kconv(const uint32_t* __restrict__ in1u, const uint32_t* __restrict__ in1d,
           const uint32_t* __restrict__ in2u, const uint32_t* __restrict__ in2d,
           const uint32_t* __restrict__ wpu,  const uint32_t* __restrict__ wpd,
           void* __restrict__ outu, void* __restrict__ outd) {
    extern __shared__ uint32_t csm[];

    int tid  = threadIdx.x;
    int lane = tid & 31, warp = tid >> 5;
    int x0 = blockIdx.x * 64;
    int y0 = blockIdx.y * 8;
    int z  = blockIdx.z;
    int b  = z & 1, st = z >> 1;
    size_t bCHW = (size_t)b*CHW;

    const uint32_t* in1 = st ? in1d : in1u;
    const uint32_t* in2 = st ? in2d : in2u;
    const uint32_t* wp  = st ? wpd  : wpu;
    void* outv          = st ? outd : outu;

    int warp_o = warp & 1;
    int warp_y = warp >> 1;         // 0..7
    int lq = lane >> 2;
    int lr = lane & 3;

    uint32_t s_base = (uint32_t)__cvta_generic_to_shared(csm);

    const int NCH = CIN/16;

    // ---- staging helpers ----
    auto stage = [&](int cb, int bufi) {
        uint32_t sb = s_base + bufi*STAGE_U32*4;
        // input: 16 ch x 10 rows x 18 quads
        for (int i = tid; i < 2880; i += 512) {
            int c   = i / 180;
            int rem = i % 180;
            int r   = rem / 18;
            int q   = rem % 18;
            int gy = y0 + r - 1;
            int gx = x0 - 4 + q*4;
            uint32_t ok = (gy >= 0 && gy < HH && gx >= 0 && gx < WW) ? 16u : 0u;
            int cg = cb*16 + c;
            const uint32_t* plane;
            if (CIN == 128 && cg >= 64) plane = in2 + bCHW + (size_t)(cg - 64)*HW;
            else                        plane = in1 + bCHW + (size_t)cg*HW;
            const uint32_t* gsrc = ok ? (plane + gy*WW + gx) : plane;
            cp16(sb + (c*PLANE + r*72 + q*4)*4, gsrc, ok);
        }
        // weights
        const uint32_t* wsrc = wp + cb*SW_U32;
        for (int i = tid; i < SW_U32/4; i += 512)
            cp16(sb + (SIN_U32 + i*4)*4, wsrc + i*4, 16);
    };

    float4 acc[2][8];
    #pragma unroll
    for (int mt = 0; mt < 2; mt++)
        #pragma unroll
        for (int nt = 0; nt < 8; nt++) acc[mt][nt] = make_float4(0.f,0.f,0.f,0.f);

    stage(0, 0);
    asm volatile("cp.async.commit_group;" ::: "memory");

    for (int cb = 0; cb < NCH; cb++) {
        if (cb + 1 < NCH) {
            stage(cb + 1, (cb + 1) & 1);
            asm volatile("cp.async.commit_group;" ::: "memory");
            asm volatile("cp.async.wait_group 1;" ::: "memory");
        } else {
            asm volatile("cp.async.wait_group 0;" ::: "memory");
        }
        __syncthreads();

        const uint32_t* sin_ = csm + (cb & 1)*STAGE_U32;
        const uint32_t* sw_  = sin_ + SIN_U32;

        #pragma unroll
        for (int t = 0; t < 9; t++) {
            int ky = t/3, kx = t - ky*3;
            int row = warp_y + ky;
            int bbase = row*72 + kx + 3 + lq;
            #pragma unroll
            for (int s = 0; s < 2; s++) {
                int aoff = (t*64 + warp_o*32)*18 + s*8 + 2*lr;
                uint2 a00 = *(const uint2*)&sw_[aoff + lq*18];
                uint2 a01 = *(const uint2*)&sw_[aoff + (lq+8)*18];
                uint2 a10 = *(const uint2*)&sw_[aoff + (lq+16)*18];
                uint2 a11 = *(const uint2*)&sw_[aoff + (lq+24)*18];
                int p0 = (s*8 + lr)*PLANE + bbase;
                int p1 = p0 + 4*PLANE;
                #pragma unroll
                for (int nt = 0; nt < 8; nt++) {
                    uint32_t b0 = sin_[p0 + 8*nt];
                    uint32_t b1 = sin_[p1 + 8*nt];
                    mma_tf32(acc[0][nt], a00.x, a01.x, a00.y, a01.y, b0, b1);
                    mma_tf32(acc[1][nt], a10.x, a11.x, a10.y, a11.y, b0, b1);
                }
            }
        }
        __syncthreads();
    }

    // ---- writeback ----
    int y = y0 + warp_y;
    #pragma unroll
    for (int mt = 0; mt < 2; mt++) {
        int o_lo = warp_o*32 + mt*16 + lq;
        #pragma unroll
        for (int nt = 0; nt < 8; nt++) {
            int x = x0 + nt*8 + 2*lr;
            float4 v = acc[mt][nt];
            size_t off = bCHW + (size_t)o_lo*HW + (size_t)y*WW + x;
            if (FUSE) {
                uint32_t* outp = (uint32_t*)outv;
                uint2 r0 = make_uint2(f2tf32(fmaxf(v.x, 0.f)), f2tf32(fmaxf(v.y, 0.f)));
                uint2 r1 = make_uint2(f2tf32(fmaxf(v.z, 0.f)), f2tf32(fmaxf(v.w, 0.f)));
                *(uint2*)(outp + off)            = r0;
                *(uint2*)(outp + off + 8*HW)     = r1;
            } else {
                float* outp = (float*)outv;
                *(float2*)(outp + off)           = make_float2(v.x, v.y);
                *(float2*)(outp + off + 8*HW)    = make_float2(v.z, v.w);
            }
        }
    }
}

// ---------------------------------------------------------------------------
extern "C" void kernel_launch(void* const* d_in, const int* in_sizes, int n_in,
                              void* d_out, int out_size) {
    const float* u   = (const float*)d_in[0];
    const float* d   = (const float*)d_in[1];
    const float* Wu1 = (const float*)d_in[2];
    const float* Wu2 = (const float*)d_in[3];
    const float* Wd1 = (const float*)d_in[4];
    const float* Wd2 = (const float*)d_in[5];
    const float* W1a = (const float*)d_in[6];
    const float* W1b = (const float*)d_in[7];
    const float* W2a = (const float*)d_in[8];
    const float* W2b = (const float*)d_in[9];
    float* out = (float*)d_out;

    cudaFuncSetAttribute(kattn, cudaFuncAttributeMaxDynamicSharedMemorySize, ATTN_SMEM);
    cudaFuncSetAttribute(kconv<128, true>,  cudaFuncAttributeMaxDynamicSharedMemorySize, CONV_SMEM);
    cudaFuncSetAttribute(kconv<64, false>,  cudaFuncAttributeMaxDynamicSharedMemorySize, CONV_SMEM);

    uint32_t *pbuf0, *pbuf1, *pt0, *pt1, *putf, *pdtf;
    uint32_t *pw1a, *pw2a, *pw1b, *pw2b;
    cudaGetSymbolAddress((void**)&pbuf0, g_buf);   pbuf1 = pbuf0 + TENSOR_ELEMS;
    cudaGetSymbolAddress((void**)&pt0,   g_t);     pt1   = pt0   + TENSOR_ELEMS;
    cudaGetSymbolAddress((void**)&putf,  g_utf);
    cudaGetSymbolAddress((void**)&pdtf,  g_dtf);
    cudaGetSymbolAddress((void**)&pw1a,  g_wp1a);
    cudaGetSymbolAddress((void**)&pw2a,  g_wp2a);
    cudaGetSymbolAddress((void**)&pw1b,  g_wp1b);
    cudaGetSymbolAddress((void**)&pw2b,  g_wp2b);

    // prep
    kprepin<<<2048, 256>>>(u, d);
    kprepw<<<(8*9*64*18 + 255)/256, 256>>>(W1a, pw1a, 128);
    kprepw<<<(8*9*64*18 + 255)/256, 256>>>(W2a, pw2a, 128);
    kprepw<<<(4*9*64*18 + 255)/256, 256>>>(W1b, pw1b, 64);
    kprepw<<<(4*9*64*18 + 255)/256, 256>>>(W2b, pw2b, 64);
    kcomputeM<<<1, 256>>>(Wu1, Wd2, 0);
    kcomputeM<<<1, 256>>>(Wd1, Wu2, 1);

    // attention (tensor core) -> tf32 buffers
    kattn<<<BB*HH, 256, ATTN_SMEM>>>(0);

    // conv1 + relu (both streams in one launch), then conv2
    dim3 grid(WW/64, HH/8, 4);
    kconv<128, true><<<grid, 512, CONV_SMEM>>>(putf, pdtf, pbuf0, pbuf1,
                                               pw1a, pw2a, pt0, pt1);
    kconv<64, false><<<grid, 512, CONV_SMEM>>>(pt0, pt1, pt0, pt1,
                                               pw1b, pw2b, out, out + TENSOR_ELEMS);
}